// round 13
// baseline (speedup 1.0000x reference)
#include <cuda_runtime.h>
#include <cuda_bf16.h>
#include <cstdint>
#include <math.h>

// ---------------- constants ----------------
#define BB   2
#define TT   2048
#define CIN  2048
#define HH   256
#define NHD  8
#define HD   32
#define NCT  19
#define NLY  6
#define FFD  1024
#define LL   2067              // TT + NCT
#define BL   (BB*LL)           // 4134
#define LSTM_CL 8              // cluster size (per batch)

// output layout: tok_cls [B*NC]=38 | fr_cls [B*T*NC]=77824 | tok [B*L*H]=1058304
#define OUT_FR_OFF   38
#define OUT_TOK_OFF  77862

// ---------------- scratch (static device memory; no allocs) ----------------
__device__ float g_tok[(size_t)BL*HH];
__device__ float g_z  [(size_t)BL*HH];
__device__ float g_qkv[(size_t)BL*3*HH];
__device__ float g_o  [(size_t)BL*HH];
__device__ float g_ffh[(size_t)BL*FFD];
__device__ float g_xg [(size_t)BL*4*HH];

// ---------------- GEMM: C[m,n] = sum_k A[m,k]*W[n,k] (+epilogue) ----------------
template<int EP, int BM>
__global__ void __launch_bounds__(256, 2)
gemm_tn(const float* __restrict__ A, const float* __restrict__ W,
        const float* __restrict__ b0, const float* __restrict__ b1,
        const float* __restrict__ aux, float* __restrict__ C,
        int M, int N, int K)
{
    constexpr int TM = BM / 16;        // rows per thread
    constexpr int NA = BM / 64;        // float4 A-loads per thread
    __shared__ float As[2][16][BM];
    __shared__ float Bs[2][16][128];
    const int tid = threadIdx.x;
    const int bm = blockIdx.y * BM;
    const int bn = blockIdx.x * 128;
    const int ar0 = tid >> 2;          // 0..63
    const int ak  = (tid & 3) * 4;     // 0,4,8,12
    const int ty = tid >> 4, tx = tid & 15;

    float acc[TM][8];
#pragma unroll
    for (int i = 0; i < TM; i++)
#pragma unroll
        for (int j = 0; j < 8; j++) acc[i][j] = 0.f;

    const int ntiles = K >> 4;
    float4 pa[NA], pb[2];

#pragma unroll
    for (int i = 0; i < NA; i++) {
        int gm = bm + ar0 + i * 64;
        pa[i] = (gm < M) ? *(const float4*)(A + (size_t)gm * K + ak)
                         : make_float4(0.f, 0.f, 0.f, 0.f);
    }
#pragma unroll
    for (int i = 0; i < 2; i++) {
        int gn = bn + ar0 + i * 64;
        pb[i] = *(const float4*)(W + (size_t)gn * K + ak);
    }
#pragma unroll
    for (int i = 0; i < NA; i++) {
        int r = ar0 + i * 64;
        As[0][ak+0][r] = pa[i].x; As[0][ak+1][r] = pa[i].y;
        As[0][ak+2][r] = pa[i].z; As[0][ak+3][r] = pa[i].w;
    }
#pragma unroll
    for (int i = 0; i < 2; i++) {
        int r = ar0 + i * 64;
        Bs[0][ak+0][r] = pb[i].x; Bs[0][ak+1][r] = pb[i].y;
        Bs[0][ak+2][r] = pb[i].z; Bs[0][ak+3][r] = pb[i].w;
    }
    __syncthreads();

    int buf = 0;
    for (int t = 0; t < ntiles; t++) {
        if (t + 1 < ntiles) {
            const int k0 = (t + 1) << 4;
#pragma unroll
            for (int i = 0; i < NA; i++) {
                int gm = bm + ar0 + i * 64;
                pa[i] = (gm < M) ? *(const float4*)(A + (size_t)gm * K + k0 + ak)
                                 : make_float4(0.f, 0.f, 0.f, 0.f);
            }
#pragma unroll
            for (int i = 0; i < 2; i++) {
                int gn = bn + ar0 + i * 64;
                pb[i] = *(const float4*)(W + (size_t)gn * K + k0 + ak);
            }
        }
#pragma unroll
        for (int k = 0; k < 16; k++) {
            float ra[TM], rb[8];
#pragma unroll
            for (int i = 0; i < TM; i++) ra[i] = As[buf][k][ty*TM + i];
#pragma unroll
            for (int j = 0; j < 8; j++) rb[j] = Bs[buf][k][tx*8 + j];
#pragma unroll
            for (int i = 0; i < TM; i++)
#pragma unroll
                for (int j = 0; j < 8; j++) acc[i][j] += ra[i] * rb[j];
        }
        if (t + 1 < ntiles) {
            const int nb = buf ^ 1;
#pragma unroll
            for (int i = 0; i < NA; i++) {
                int r = ar0 + i * 64;
                As[nb][ak+0][r] = pa[i].x; As[nb][ak+1][r] = pa[i].y;
                As[nb][ak+2][r] = pa[i].z; As[nb][ak+3][r] = pa[i].w;
            }
#pragma unroll
            for (int i = 0; i < 2; i++) {
                int r = ar0 + i * 64;
                Bs[nb][ak+0][r] = pb[i].x; Bs[nb][ak+1][r] = pb[i].y;
                Bs[nb][ak+2][r] = pb[i].z; Bs[nb][ak+3][r] = pb[i].w;
            }
        }
        __syncthreads();
        buf ^= 1;
    }

#pragma unroll
    for (int i = 0; i < TM; i++) {
        int m = bm + ty*TM + i;
        if (m >= M) continue;
        if (EP == 3) {
            int bb = m >> 11;          // m / T
            int tt = m & (TT-1);       // m % T
            float* cp = C + ((size_t)(bb*LL + NCT + tt)) * HH + bn + tx*8;
            const float* pe = aux + (size_t)tt * HH + bn + tx*8;
#pragma unroll
            for (int j = 0; j < 8; j++)
                cp[j] = acc[i][j] + b0[bn + tx*8 + j] + pe[j];
        } else {
            float* cp = C + (size_t)m * N + bn + tx*8;
#pragma unroll
            for (int j = 0; j < 8; j++) {
                float v = acc[i][j] + b0[bn + tx*8 + j];
                if (EP == 1) v = fmaxf(v, 0.f);
                if (EP == 2) v += cp[j];
                if (EP == 4) v += b1[bn + tx*8 + j];
                cp[j] = v;
            }
        }
    }
}

// ---------------- LayerNorm (row = 256) ----------------
__global__ void ln_kernel(const float* __restrict__ x, const float* __restrict__ g,
                          const float* __restrict__ b, float* __restrict__ y)
{
    int row = blockIdx.x, t = threadIdx.x;
    float v = x[(size_t)row * HH + t];
    float s = v, s2 = v * v;
#pragma unroll
    for (int o = 16; o; o >>= 1) {
        s  += __shfl_xor_sync(~0u, s,  o);
        s2 += __shfl_xor_sync(~0u, s2, o);
    }
    __shared__ float ss[8], ss2[8];
    __shared__ float smean, srstd;
    if ((t & 31) == 0) { ss[t>>5] = s; ss2[t>>5] = s2; }
    __syncthreads();
    if (t == 0) {
        float S = 0.f, S2 = 0.f;
#pragma unroll
        for (int i = 0; i < 8; i++) { S += ss[i]; S2 += ss2[i]; }
        float m = S * (1.f/HH);
        float var = S2 * (1.f/HH) - m * m;
        smean = m; srstd = rsqrtf(var + 1e-5f);
    }
    __syncthreads();
    y[(size_t)row * HH + t] = (v - smean) * srstd * g[t] + b[t];
}

// ---------------- banded attention, SMEM-staged K (warp per query) ----------------
template<bool CLS>
__global__ void attn_kernel2(const float* __restrict__ qkv, float* __restrict__ o, int r)
{
    constexpr int SCN = CLS ? LL : 96;
    __shared__ alignas(16) float sc[SCN];
    __shared__ alignas(16) float ks[32][36];
    const int bid = blockIdx.x;
    const int lane = threadIdx.x;
    int ql, h, b, nk, lo = 0;
    if (CLS) {
        ql = bid % NCT; h = (bid / NCT) & (NHD-1); b = bid / (NCT*NHD);
        nk = LL;
    } else {
        int j = bid % TT; h = (bid / TT) & (NHD-1); b = bid / (TT*NHD);
        ql = NCT + j;
        lo = j - r; if (lo < 0) lo = 0;
        int hi = j + r; if (hi > TT-1) hi = TT-1;
        nk = NCT + hi - lo + 1;
    }
    const float scale = 0.17677669529663687f; // 1/sqrt(32)

    const float* qp = qkv + ((size_t)(b*LL + ql)) * 768 + h*HD;
    float qreg[HD];
#pragma unroll
    for (int d = 0; d < HD; d++) qreg[d] = qp[d] * scale;

    float mx = -1e30f;
    for (int base = 0; base < nk; base += 32) {
        int cnt = nk - base; if (cnt > 32) cnt = 32;
        for (int kk = 0; kk < cnt; kk++) {
            int n = base + kk;
            int kr = CLS ? n : (n < NCT ? n : NCT + lo + (n - NCT));
            ks[kk][lane] = qkv[((size_t)(b*LL + kr)) * 768 + HH + h*HD + lane];
        }
        __syncwarp();
        if (lane < cnt) {
            const float4* kp4 = (const float4*)ks[lane];
            float s = 0.f;
#pragma unroll
            for (int d4 = 0; d4 < 8; d4++) {
                float4 k4 = kp4[d4];
                s += qreg[4*d4+0]*k4.x + qreg[4*d4+1]*k4.y
                   + qreg[4*d4+2]*k4.z + qreg[4*d4+3]*k4.w;
            }
            sc[base + lane] = s;
            mx = fmaxf(mx, s);
        }
        __syncwarp();
    }
#pragma unroll
    for (int m = 16; m; m >>= 1) mx = fmaxf(mx, __shfl_xor_sync(~0u, mx, m));
    float sum = 0.f;
    for (int n = lane; n < nk; n += 32) {
        float e = __expf(sc[n] - mx);
        sc[n] = e;
        sum += e;
    }
#pragma unroll
    for (int m = 16; m; m >>= 1) sum += __shfl_xor_sync(~0u, sum, m);
    __syncwarp();
    float inv = 1.f / sum;

    float accd = 0.f;
    for (int n = 0; n < nk; n++) {
        int kr = CLS ? n : (n < NCT ? n : NCT + lo + (n - NCT));
        accd += sc[n] * qkv[((size_t)(b*LL + kr)) * 768 + 2*HH + h*HD + lane];
    }
    o[((size_t)(b*LL + ql)) * HH + h*HD + lane] = accd * inv;
}

// ---------------- LSTM: 2 clusters of 8 CTAs, single-hop per-unit release-flag publish ----------------
// Producer lane: plain remote store of h value, then st.release of a per-unit
// 32-bit tag. Release orders the SAME thread's prior data store — no cross-lane
// fence, no drain, data+flag fly in one hop. Consumer polls its 64 tags with
// volatile LDS.128 (tag >= t, monotonic), one cheap acq_rel fence, plain-LDS dot.
// Double buffering is race-free: a producer can only advance a buffer after
// every CTA has published the previous step, which requires their reads done.
__device__ __forceinline__ float tanh_f(float x)
{
    x = fminf(fmaxf(x, -15.f), 15.f);
    float e = __expf(2.f * x);
    return __fdividef(e - 1.f, e + 1.f);
}

__global__ void __cluster_dims__(LSTM_CL, 1, 1) __launch_bounds__(512, 1)
lstm_rec(const float* __restrict__ xg, const float* __restrict__ whh,
         float* __restrict__ tok)
{
    const int tid  = threadIdx.x;         // 512
    const int lane = tid & 31;
    const int rl   = tid >> 2;            // local gate-row 0..127
    const int q    = tid & 3;             // k-chunk (64 h each)
    const int g    = rl >> 5;             // gate 0..3
    const int ul   = rl & 31;             // local unit 0..31
    uint32_t rank;
    asm("mov.u32 %0, %%cluster_ctarank;" : "=r"(rank));
    const int bb  = blockIdx.x >> 3;      // batch (cluster id)
    const int row = g * HH + (int)rank * 32 + ul;   // global gate row

    // 64 recurrent weights per thread, register-resident for all steps
    float wr[64];
    {
        const float* wp = whh + (size_t)row * HH + q * 64;
#pragma unroll
        for (int i = 0; i < 64; i += 4) {
            float4 v = *(const float4*)(wp + i);
            wr[i] = v.x; wr[i+1] = v.y; wr[i+2] = v.z; wr[i+3] = v.w;
        }
    }

    __shared__ alignas(16) float    hval[2][HH];   // double-buffered h values
    __shared__ alignas(16) unsigned hflg[2][HH];   // per-unit tags (t of the h stored)
    __shared__ float gred[128];
    __shared__ float cst[32];

    // init: buffer0 holds h(0)=0 with tag 0; buffer1 tag 0 (< any needed t>=1)
    for (int i = tid; i < 2*HH; i += 512) {
        ((float*)hval)[i] = 0.f;
        ((unsigned*)hflg)[i] = 0u;
    }
    if (tid < 32) cst[tid] = 0.f;
    __syncthreads();
    // peers must not remote-store before our init is done
    asm volatile("barrier.cluster.arrive.aligned;" ::: "memory");
    asm volatile("barrier.cluster.wait.aligned;" ::: "memory");

    const uint32_t vb0 = (uint32_t)__cvta_generic_to_shared(&hval[0][0]);
    const uint32_t vb1 = (uint32_t)__cvta_generic_to_shared(&hval[1][0]);
    const uint32_t fb0 = (uint32_t)__cvta_generic_to_shared(&hflg[0][0]);
    const uint32_t fb1 = (uint32_t)__cvta_generic_to_shared(&hflg[1][0]);
    // my unit's value/flag slots in each buffer (gate warp only)
    uint32_t la_v[2], la_f[2];
    la_v[0] = vb0 + ((uint32_t)rank * 32 + lane) * 4;
    la_v[1] = vb1 + ((uint32_t)rank * 32 + lane) * 4;
    la_f[0] = fb0 + ((uint32_t)rank * 32 + lane) * 4;
    la_f[1] = fb1 + ((uint32_t)rank * 32 + lane) * 4;

    size_t xg_off = ((size_t)bb * LL) * (4*HH) + row;
    float xg_cur = (q == 0) ? __ldg(xg + xg_off) : 0.f;

    for (int t = 0; t < LL; t++) {
        // wait for my chunk's 64 h(t) units in buffer t&1 (tag >= t, monotonic)
        {
            const unsigned tgt = (unsigned)t;
            const uint32_t fb = ((t & 1) ? fb1 : fb0) + (uint32_t)q * 256u;
            bool ok;
            unsigned guard = 0;
            do {
                ok = true;
#pragma unroll
                for (int j = 0; j < 16; j++) {
                    unsigned f0, f1, f2, f3;
                    asm volatile("ld.volatile.shared.v4.u32 {%0,%1,%2,%3}, [%4];"
                                 : "=r"(f0), "=r"(f1), "=r"(f2), "=r"(f3)
                                 : "r"(fb + (uint32_t)j * 16u));
                    ok = ok && (f0 >= tgt) && (f1 >= tgt) && (f2 >= tgt) && (f3 >= tgt);
                }
            } while (!ok && ++guard < (1u << 16));   // watchdog: fail visibly, never hang
            asm volatile("fence.acq_rel.cluster;" ::: "memory");
        }
        // prefetch next xg off the critical path
        float xg_next = (q == 0 && t + 1 < LL) ? __ldg(xg + xg_off + 4*HH) : 0.f;

        const float4* hp = (const float4*)&hval[t & 1][q * 64];
        float a0 = 0.f, a1 = 0.f, a2 = 0.f, a3 = 0.f;
#pragma unroll
        for (int i = 0; i < 16; i++) {
            float4 h4 = hp[i];
            a0 += wr[4*i+0] * h4.x; a1 += wr[4*i+1] * h4.y;
            a2 += wr[4*i+2] * h4.z; a3 += wr[4*i+3] * h4.w;
        }
        float a = (a0 + a1) + (a2 + a3);
        a += __shfl_xor_sync(~0u, a, 1);
        a += __shfl_xor_sync(~0u, a, 2);
        if (q == 0) gred[rl] = a + xg_cur;
        __syncthreads();

        if (tid < 32) {
            float gi = gred[tid];
            float gf = gred[32 + tid];
            float gg = gred[64 + tid];
            float go = gred[96 + tid];
            float iv = __fdividef(1.f, 1.f + __expf(-gi));
            float fv = __fdividef(1.f, 1.f + __expf(-gf));
            float ov = __fdividef(1.f, 1.f + __expf(-go));
            float cv = fv * cst[tid] + iv * tanh_f(gg);
            float hv = ov * tanh_f(cv);
            cst[tid] = cv;
            tok[((size_t)(bb*LL + t)) * HH + rank*32 + tid] = hv;
            // single-hop publish of h(t+1): value store + release-tag store per peer
            const unsigned tag = (unsigned)(t + 1);
            const uint32_t lav = la_v[(t + 1) & 1];
            const uint32_t laf = la_f[(t + 1) & 1];
#pragma unroll
            for (int rr = 0; rr < LSTM_CL; rr++) {
                uint32_t rav, raf;
                asm volatile("mapa.shared::cluster.u32 %0, %1, %2;"
                             : "=r"(rav) : "r"(lav), "r"(rr));
                asm volatile("st.shared::cluster.f32 [%0], %1;"
                             :: "r"(rav), "f"(hv) : "memory");
                asm volatile("mapa.shared::cluster.u32 %0, %1, %2;"
                             : "=r"(raf) : "r"(laf), "r"(rr));
                asm volatile("st.release.cluster.shared::cluster.u32 [%0], %1;"
                             :: "r"(raf), "r"(tag) : "memory");
            }
        }
        xg_cur = xg_next;
        xg_off += 4*HH;
    }
    // no CTA may exit while peers might still remote-store into it
    asm volatile("barrier.cluster.arrive.aligned;" ::: "memory");
    asm volatile("barrier.cluster.wait.aligned;" ::: "memory");
}

// ---------------- misc small kernels ----------------
__global__ void fill_cls(const float* __restrict__ ct, float* __restrict__ tok)
{
    int i = blockIdx.x * blockDim.x + threadIdx.x;
    if (i >= BB*NCT*HH) return;
    int n = i & (HH-1);
    int c = (i >> 8) % NCT;
    int b = i / (NCT*HH);
    tok[((size_t)(b*LL + c)) * HH + n] = ct[c*HH + n];
}

__global__ void head_kernel(const float* __restrict__ tok, const float* __restrict__ cw,
                            const float* __restrict__ cb, float* __restrict__ out)
{
    int m = blockIdx.x;           // 0..BL-1
    int lane = threadIdx.x;       // 32
    int b = m / LL, l = m % LL;
    __shared__ float tr[HH];
    const float* trow = tok + (size_t)m * HH;
    for (int i = lane; i < HH; i += 32) tr[i] = trow[i];
    __syncwarp();
    if (l < NCT) {
        float sum = 0.f;
        for (int i = lane; i < HH; i += 32) sum += tr[i] * cw[l*HH + i];
#pragma unroll
        for (int o = 16; o; o >>= 1) sum += __shfl_xor_sync(~0u, sum, o);
        if (lane == 0) out[b*NCT + l] = sum + cb[l];
    } else {
        if (lane < NCT) {
            float sum = 0.f;
#pragma unroll 8
            for (int i = 0; i < HH; i++) sum += tr[i] * cw[lane*HH + i];
            out[OUT_FR_OFF + ((size_t)(b*TT + (l - NCT))) * NCT + lane] = sum + cb[lane];
        }
    }
}

__global__ void copy_kernel(const float* __restrict__ src, float* __restrict__ dst, int n)
{
    int i = blockIdx.x * blockDim.x + threadIdx.x;
    if (i < n) dst[i] = src[i];
}

// ---------------- launch ----------------
extern "C" void kernel_launch(void* const* d_in, const int* in_sizes, int n_in,
                              void* d_out, int out_size)
{
    const float* x         = (const float*)d_in[0];
    const float* in_proj_w = (const float*)d_in[2];
    const float* in_proj_b = (const float*)d_in[3];
    const float* pos_emb   = (const float*)d_in[4];
    const float* cls_tok   = (const float*)d_in[5];
    const float* qkv_w     = (const float*)d_in[6];
    const float* qkv_b     = (const float*)d_in[7];
    const float* out_w     = (const float*)d_in[8];
    const float* out_b     = (const float*)d_in[9];
    const float* ln1_g     = (const float*)d_in[10];
    const float* ln1_b     = (const float*)d_in[11];
    const float* ln2_g     = (const float*)d_in[12];
    const float* ln2_b     = (const float*)d_in[13];
    const float* ff1_w     = (const float*)d_in[14];
    const float* ff1_b     = (const float*)d_in[15];
    const float* ff2_w     = (const float*)d_in[16];
    const float* ff2_b     = (const float*)d_in[17];
    const float* lstm_wih  = (const float*)d_in[18];
    const float* lstm_whh  = (const float*)d_in[19];
    const float* lstm_bih  = (const float*)d_in[20];
    const float* lstm_bhh  = (const float*)d_in[21];
    const float* cls_w     = (const float*)d_in[22];
    const float* cls_b     = (const float*)d_in[23];
    float* out = (float*)d_out;

    float *tok, *z, *qkvb, *ob, *ffh, *xg;
    cudaGetSymbolAddress((void**)&tok,  g_tok);
    cudaGetSymbolAddress((void**)&z,    g_z);
    cudaGetSymbolAddress((void**)&qkvb, g_qkv);
    cudaGetSymbolAddress((void**)&ob,   g_o);
    cudaGetSymbolAddress((void**)&ffh,  g_ffh);
    cudaGetSymbolAddress((void**)&xg,   g_xg);

    fill_cls<<<(BB*NCT*HH + 255)/256, 256>>>(cls_tok, tok);
    gemm_tn<3,64><<<dim3(2, 64), 256>>>(x, in_proj_w, in_proj_b, nullptr, pos_emb,
                                        tok, BB*TT, HH, CIN);

    for (int i = 0; i < NLY; i++) {
        if (i == 3) {
            gemm_tn<4,64><<<dim3(8, 65), 256>>>(tok, lstm_wih, lstm_bih, lstm_bhh, nullptr,
                                                xg, BL, 4*HH, HH);
            lstm_rec<<<2*LSTM_CL, 512>>>(xg, lstm_whh, tok);
        }
        ln_kernel<<<BL, HH>>>(tok, ln1_g + i*HH, ln1_b + i*HH, z);
        gemm_tn<0,64><<<dim3(6, 65), 256>>>(z, qkv_w + (size_t)i*3*HH*HH, qkv_b + i*3*HH,
                                            nullptr, nullptr, qkvb, BL, 3*HH, HH);
        int r = 1 << i; if (r > TT-1) r = TT-1;
        attn_kernel2<false><<<BB*NHD*TT, 32>>>(qkvb, ob, r);
        attn_kernel2<true><<<BB*NHD*NCT, 32>>>(qkvb, ob, r);
        gemm_tn<2,64><<<dim3(2, 65), 256>>>(ob, out_w + (size_t)i*HH*HH, out_b + i*HH,
                                            nullptr, nullptr, tok, BL, HH, HH);
        ln_kernel<<<BL, HH>>>(tok, ln2_g + i*HH, ln2_b + i*HH, z);
        gemm_tn<1,64><<<dim3(8, 65), 256>>>(z, ff1_w + (size_t)i*FFD*HH, ff1_b + i*FFD,
                                            nullptr, nullptr, ffh, BL, FFD, HH);
        gemm_tn<2,64><<<dim3(2, 65), 256>>>(ffh, ff2_w + (size_t)i*HH*FFD, ff2_b + i*HH,
                                            nullptr, nullptr, tok, BL, HH, FFD);
    }

    head_kernel<<<BL, 32>>>(tok, cls_w, cls_b, out);
    copy_kernel<<<(BL*HH + 255)/256, 256>>>(tok, out + OUT_TOK_OFF, BL*HH);
}

// round 14
// speedup vs baseline: 2.1479x; 2.1479x over previous
#include <cuda_runtime.h>
#include <cuda_bf16.h>
#include <cstdint>
#include <math.h>

// ---------------- constants ----------------
#define BB   2
#define TT   2048
#define CIN  2048
#define HH   256
#define NHD  8
#define HD   32
#define NCT  19
#define NLY  6
#define FFD  1024
#define LL   2067              // TT + NCT
#define BL   (BB*LL)           // 4134
#define LSTM_CL 8              // cluster size (per batch)

// output layout: tok_cls [B*NC]=38 | fr_cls [B*T*NC]=77824 | tok [B*L*H]=1058304
#define OUT_FR_OFF   38
#define OUT_TOK_OFF  77862

// ---------------- scratch (static device memory; no allocs) ----------------
__device__ float g_tok[(size_t)BL*HH];
__device__ float g_z  [(size_t)BL*HH];
__device__ float g_qkv[(size_t)BL*3*HH];
__device__ float g_o  [(size_t)BL*HH];
__device__ float g_ffh[(size_t)BL*FFD];
__device__ float g_xg [(size_t)BL*4*HH];

// ---------------- GEMM: C[m,n] = sum_k A[m,k]*W[n,k] (+epilogue) ----------------
template<int EP, int BM>
__global__ void __launch_bounds__(256, 2)
gemm_tn(const float* __restrict__ A, const float* __restrict__ W,
        const float* __restrict__ b0, const float* __restrict__ b1,
        const float* __restrict__ aux, float* __restrict__ C,
        int M, int N, int K)
{
    constexpr int TM = BM / 16;        // rows per thread
    constexpr int NA = BM / 64;        // float4 A-loads per thread
    __shared__ float As[2][16][BM];
    __shared__ float Bs[2][16][128];
    const int tid = threadIdx.x;
    const int bm = blockIdx.y * BM;
    const int bn = blockIdx.x * 128;
    const int ar0 = tid >> 2;          // 0..63
    const int ak  = (tid & 3) * 4;     // 0,4,8,12
    const int ty = tid >> 4, tx = tid & 15;

    float acc[TM][8];
#pragma unroll
    for (int i = 0; i < TM; i++)
#pragma unroll
        for (int j = 0; j < 8; j++) acc[i][j] = 0.f;

    const int ntiles = K >> 4;
    float4 pa[NA], pb[2];

#pragma unroll
    for (int i = 0; i < NA; i++) {
        int gm = bm + ar0 + i * 64;
        pa[i] = (gm < M) ? *(const float4*)(A + (size_t)gm * K + ak)
                         : make_float4(0.f, 0.f, 0.f, 0.f);
    }
#pragma unroll
    for (int i = 0; i < 2; i++) {
        int gn = bn + ar0 + i * 64;
        pb[i] = *(const float4*)(W + (size_t)gn * K + ak);
    }
#pragma unroll
    for (int i = 0; i < NA; i++) {
        int r = ar0 + i * 64;
        As[0][ak+0][r] = pa[i].x; As[0][ak+1][r] = pa[i].y;
        As[0][ak+2][r] = pa[i].z; As[0][ak+3][r] = pa[i].w;
    }
#pragma unroll
    for (int i = 0; i < 2; i++) {
        int r = ar0 + i * 64;
        Bs[0][ak+0][r] = pb[i].x; Bs[0][ak+1][r] = pb[i].y;
        Bs[0][ak+2][r] = pb[i].z; Bs[0][ak+3][r] = pb[i].w;
    }
    __syncthreads();

    int buf = 0;
    for (int t = 0; t < ntiles; t++) {
        if (t + 1 < ntiles) {
            const int k0 = (t + 1) << 4;
#pragma unroll
            for (int i = 0; i < NA; i++) {
                int gm = bm + ar0 + i * 64;
                pa[i] = (gm < M) ? *(const float4*)(A + (size_t)gm * K + k0 + ak)
                                 : make_float4(0.f, 0.f, 0.f, 0.f);
            }
#pragma unroll
            for (int i = 0; i < 2; i++) {
                int gn = bn + ar0 + i * 64;
                pb[i] = *(const float4*)(W + (size_t)gn * K + k0 + ak);
            }
        }
#pragma unroll
        for (int k = 0; k < 16; k++) {
            float ra[TM], rb[8];
#pragma unroll
            for (int i = 0; i < TM; i++) ra[i] = As[buf][k][ty*TM + i];
#pragma unroll
            for (int j = 0; j < 8; j++) rb[j] = Bs[buf][k][tx*8 + j];
#pragma unroll
            for (int i = 0; i < TM; i++)
#pragma unroll
                for (int j = 0; j < 8; j++) acc[i][j] += ra[i] * rb[j];
        }
        if (t + 1 < ntiles) {
            const int nb = buf ^ 1;
#pragma unroll
            for (int i = 0; i < NA; i++) {
                int r = ar0 + i * 64;
                As[nb][ak+0][r] = pa[i].x; As[nb][ak+1][r] = pa[i].y;
                As[nb][ak+2][r] = pa[i].z; As[nb][ak+3][r] = pa[i].w;
            }
#pragma unroll
            for (int i = 0; i < 2; i++) {
                int r = ar0 + i * 64;
                Bs[nb][ak+0][r] = pb[i].x; Bs[nb][ak+1][r] = pb[i].y;
                Bs[nb][ak+2][r] = pb[i].z; Bs[nb][ak+3][r] = pb[i].w;
            }
        }
        __syncthreads();
        buf ^= 1;
    }

#pragma unroll
    for (int i = 0; i < TM; i++) {
        int m = bm + ty*TM + i;
        if (m >= M) continue;
        if (EP == 3) {
            int bb = m >> 11;          // m / T
            int tt = m & (TT-1);       // m % T
            float* cp = C + ((size_t)(bb*LL + NCT + tt)) * HH + bn + tx*8;
            const float* pe = aux + (size_t)tt * HH + bn + tx*8;
#pragma unroll
            for (int j = 0; j < 8; j++)
                cp[j] = acc[i][j] + b0[bn + tx*8 + j] + pe[j];
        } else {
            float* cp = C + (size_t)m * N + bn + tx*8;
#pragma unroll
            for (int j = 0; j < 8; j++) {
                float v = acc[i][j] + b0[bn + tx*8 + j];
                if (EP == 1) v = fmaxf(v, 0.f);
                if (EP == 2) v += cp[j];
                if (EP == 4) v += b1[bn + tx*8 + j];
                cp[j] = v;
            }
        }
    }
}

// ---------------- LayerNorm (row = 256) ----------------
__global__ void ln_kernel(const float* __restrict__ x, const float* __restrict__ g,
                          const float* __restrict__ b, float* __restrict__ y)
{
    int row = blockIdx.x, t = threadIdx.x;
    float v = x[(size_t)row * HH + t];
    float s = v, s2 = v * v;
#pragma unroll
    for (int o = 16; o; o >>= 1) {
        s  += __shfl_xor_sync(~0u, s,  o);
        s2 += __shfl_xor_sync(~0u, s2, o);
    }
    __shared__ float ss[8], ss2[8];
    __shared__ float smean, srstd;
    if ((t & 31) == 0) { ss[t>>5] = s; ss2[t>>5] = s2; }
    __syncthreads();
    if (t == 0) {
        float S = 0.f, S2 = 0.f;
#pragma unroll
        for (int i = 0; i < 8; i++) { S += ss[i]; S2 += ss2[i]; }
        float m = S * (1.f/HH);
        float var = S2 * (1.f/HH) - m * m;
        smean = m; srstd = rsqrtf(var + 1e-5f);
    }
    __syncthreads();
    y[(size_t)row * HH + t] = (v - smean) * srstd * g[t] + b[t];
}

// ---------------- banded attention, SMEM-staged K (warp per query) ----------------
template<bool CLS>
__global__ void attn_kernel2(const float* __restrict__ qkv, float* __restrict__ o, int r)
{
    constexpr int SCN = CLS ? LL : 96;
    __shared__ alignas(16) float sc[SCN];
    __shared__ alignas(16) float ks[32][36];
    const int bid = blockIdx.x;
    const int lane = threadIdx.x;
    int ql, h, b, nk, lo = 0;
    if (CLS) {
        ql = bid % NCT; h = (bid / NCT) & (NHD-1); b = bid / (NCT*NHD);
        nk = LL;
    } else {
        int j = bid % TT; h = (bid / TT) & (NHD-1); b = bid / (TT*NHD);
        ql = NCT + j;
        lo = j - r; if (lo < 0) lo = 0;
        int hi = j + r; if (hi > TT-1) hi = TT-1;
        nk = NCT + hi - lo + 1;
    }
    const float scale = 0.17677669529663687f; // 1/sqrt(32)

    const float* qp = qkv + ((size_t)(b*LL + ql)) * 768 + h*HD;
    float qreg[HD];
#pragma unroll
    for (int d = 0; d < HD; d++) qreg[d] = qp[d] * scale;

    float mx = -1e30f;
    for (int base = 0; base < nk; base += 32) {
        int cnt = nk - base; if (cnt > 32) cnt = 32;
        for (int kk = 0; kk < cnt; kk++) {
            int n = base + kk;
            int kr = CLS ? n : (n < NCT ? n : NCT + lo + (n - NCT));
            ks[kk][lane] = qkv[((size_t)(b*LL + kr)) * 768 + HH + h*HD + lane];
        }
        __syncwarp();
        if (lane < cnt) {
            const float4* kp4 = (const float4*)ks[lane];
            float s = 0.f;
#pragma unroll
            for (int d4 = 0; d4 < 8; d4++) {
                float4 k4 = kp4[d4];
                s += qreg[4*d4+0]*k4.x + qreg[4*d4+1]*k4.y
                   + qreg[4*d4+2]*k4.z + qreg[4*d4+3]*k4.w;
            }
            sc[base + lane] = s;
            mx = fmaxf(mx, s);
        }
        __syncwarp();
    }
#pragma unroll
    for (int m = 16; m; m >>= 1) mx = fmaxf(mx, __shfl_xor_sync(~0u, mx, m));
    float sum = 0.f;
    for (int n = lane; n < nk; n += 32) {
        float e = __expf(sc[n] - mx);
        sc[n] = e;
        sum += e;
    }
#pragma unroll
    for (int m = 16; m; m >>= 1) sum += __shfl_xor_sync(~0u, sum, m);
    __syncwarp();
    float inv = 1.f / sum;

    float accd = 0.f;
    for (int n = 0; n < nk; n++) {
        int kr = CLS ? n : (n < NCT ? n : NCT + lo + (n - NCT));
        accd += sc[n] * qkv[((size_t)(b*LL + kr)) * 768 + 2*HH + h*HD + lane];
    }
    o[((size_t)(b*LL + ql)) * HH + h*HD + lane] = accd * inv;
}

// ---------------- LSTM: 2 clusters of 8 CTAs, cp.async.bulk h exchange ----------------
// Producer gate warp: STS 32 h floats to a 128B staging buffer, fence.proxy.async
// (CTA-local, cheap), then lanes 0-7 each issue ONE cp.async.bulk (128B) to a
// peer's double-buffered h array with mbarrier complete_tx. No cluster fence, no
// store-drain (the R7/R12 cost: MEMBAR = 36 + k*n_STS with 256 in-flight stores).
// Consumer: mbarrier.try_wait.parity.acquire (guarded — no hang possible), then
// plain LDS dot. expect_tx re-armed for t+2 right after each wait (ordering:
// arm < own publish h(t+1) < any peer consuming h(t+1) < peer sends h(t+2)).
__device__ __forceinline__ float tanh_f(float x)
{
    x = fminf(fmaxf(x, -15.f), 15.f);
    float e = __expf(2.f * x);
    return __fdividef(e - 1.f, e + 1.f);
}

__device__ __forceinline__ void mbar_wait_guarded(uint32_t mbar, uint32_t parity)
{
    uint32_t done = 0;
    unsigned guard = 0;
    do {
        asm volatile(
            "{\n\t.reg .pred p;\n\t"
            "mbarrier.try_wait.parity.acquire.cta.shared::cta.b64 p, [%1], %2, 0x989680;\n\t"
            "selp.b32 %0, 1, 0, p;\n\t}"
            : "=r"(done) : "r"(mbar), "r"(parity) : "memory");
    } while (!done && ++guard < 4096u);   // bounded: protocol bug -> wrong answer, not hang
}

__global__ void __cluster_dims__(LSTM_CL, 1, 1) __launch_bounds__(512, 1)
lstm_rec(const float* __restrict__ xg, const float* __restrict__ whh,
         float* __restrict__ tok)
{
    const int tid  = threadIdx.x;         // 512
    const int lane = tid & 31;
    const int rl   = tid >> 2;            // local gate-row 0..127
    const int q    = tid & 3;             // k-chunk (64 h each)
    const int g    = rl >> 5;             // gate 0..3
    const int ul   = rl & 31;             // local unit 0..31
    uint32_t rank;
    asm("mov.u32 %0, %%cluster_ctarank;" : "=r"(rank));
    const int bb  = blockIdx.x >> 3;      // batch (cluster id)
    const int row = g * HH + (int)rank * 32 + ul;   // global gate row

    // 64 recurrent weights per thread, register-resident for all steps
    float wr[64];
    {
        const float* wp = whh + (size_t)row * HH + q * 64;
#pragma unroll
        for (int i = 0; i < 64; i += 4) {
            float4 v = *(const float4*)(wp + i);
            wr[i] = v.x; wr[i+1] = v.y; wr[i+2] = v.z; wr[i+3] = v.w;
        }
    }

    __shared__ alignas(16) float hval[2][HH];   // double-buffered h
    __shared__ alignas(16) float stg[32];       // 128B staging for bulk copy
    __shared__ float gred[128];
    __shared__ float cst[32];
    __shared__ alignas(8) unsigned long long mbar[2];

    for (int i = tid; i < 2*HH; i += 512) ((float*)hval)[i] = 0.f;
    if (tid < 32) cst[tid] = 0.f;
    const uint32_t mb0 = (uint32_t)__cvta_generic_to_shared(&mbar[0]);
    const uint32_t mb1 = (uint32_t)__cvta_generic_to_shared(&mbar[1]);
    if (tid == 0) {
        asm volatile("mbarrier.init.shared.b64 [%0], %1;" :: "r"(mb0), "r"(1u) : "memory");
        asm volatile("mbarrier.init.shared.b64 [%0], %1;" :: "r"(mb1), "r"(1u) : "memory");
        // slot1 first use is t=1 (h(1) arrives during step 0): arm now
        asm volatile("mbarrier.arrive.expect_tx.shared.b64 _, [%0], %1;"
                     :: "r"(mb1), "r"(128u * LSTM_CL) : "memory");
    }
    __syncthreads();
    // peers must not bulk-write before our init is done
    asm volatile("barrier.cluster.arrive.aligned;" ::: "memory");
    asm volatile("barrier.cluster.wait.aligned;" ::: "memory");

    const uint32_t hv_b[2] = {
        (uint32_t)__cvta_generic_to_shared(&hval[0][0]),
        (uint32_t)__cvta_generic_to_shared(&hval[1][0])
    };
    const uint32_t mb_b[2] = { mb0, mb1 };
    const uint32_t stg_a = (uint32_t)__cvta_generic_to_shared(&stg[0]);

    size_t xg_off = ((size_t)bb * LL) * (4*HH) + row;
    float xg_cur = (q == 0) ? __ldg(xg + xg_off) : 0.f;
    uint32_t ph[2] = {0u, 0u};

    for (int t = 0; t < LL; t++) {
        const int slot = t & 1;
        if (t > 0) {
            mbar_wait_guarded(mb_b[slot], ph[slot]);
            ph[slot] ^= 1u;
        }
        // re-arm this slot for its next use (t+2); arm precedes our publish of
        // h(t+1), which precedes any peer's send of h(t+2) -> race-free
        if (tid == 0 && t + 2 < LL) {
            asm volatile("mbarrier.arrive.expect_tx.shared.b64 _, [%0], %1;"
                         :: "r"(mb_b[slot]), "r"(128u * LSTM_CL) : "memory");
        }
        // prefetch next xg off the critical path
        float xg_next = (q == 0 && t + 1 < LL) ? __ldg(xg + xg_off + 4*HH) : 0.f;

        const float4* hp = (const float4*)&hval[slot][q * 64];
        float a0 = 0.f, a1 = 0.f, a2 = 0.f, a3 = 0.f;
#pragma unroll
        for (int i = 0; i < 16; i++) {
            float4 h4 = hp[i];
            a0 += wr[4*i+0] * h4.x; a1 += wr[4*i+1] * h4.y;
            a2 += wr[4*i+2] * h4.z; a3 += wr[4*i+3] * h4.w;
        }
        float a = (a0 + a1) + (a2 + a3);
        a += __shfl_xor_sync(~0u, a, 1);
        a += __shfl_xor_sync(~0u, a, 2);
        if (q == 0) gred[rl] = a + xg_cur;
        __syncthreads();

        if (tid < 32) {
            float gi = gred[tid];
            float gf = gred[32 + tid];
            float gg = gred[64 + tid];
            float go = gred[96 + tid];
            float iv = __fdividef(1.f, 1.f + __expf(-gi));
            float fv = __fdividef(1.f, 1.f + __expf(-gf));
            float ov = __fdividef(1.f, 1.f + __expf(-go));
            float cv = fv * cst[tid] + iv * tanh_f(gg);
            float hv = ov * tanh_f(cv);
            cst[tid] = cv;
            tok[((size_t)(bb*LL + t)) * HH + rank*32 + tid] = hv;
            if (t + 1 < LL) {
                // stage h(t+1) locally, then one 128B bulk copy per peer
                stg[lane] = hv;
                asm volatile("fence.proxy.async.shared::cta;" ::: "memory");
                __syncwarp();
                if (lane < LSTM_CL) {
                    const uint32_t dst_l = hv_b[(t + 1) & 1] + rank * 128u;
                    const uint32_t mbl   = mb_b[(t + 1) & 1];
                    uint32_t dst, mbp;
                    asm volatile("mapa.shared::cluster.u32 %0, %1, %2;"
                                 : "=r"(dst) : "r"(dst_l), "r"(lane));
                    asm volatile("mapa.shared::cluster.u32 %0, %1, %2;"
                                 : "=r"(mbp) : "r"(mbl), "r"(lane));
                    asm volatile(
                        "cp.async.bulk.shared::cluster.shared::cta.mbarrier::complete_tx::bytes "
                        "[%0], [%1], %2, [%3];"
                        :: "r"(dst), "r"(stg_a), "r"(128u), "r"(mbp) : "memory");
                }
            }
        }
        xg_cur = xg_next;
        xg_off += 4*HH;
    }
    // no CTA may exit while peers might still write into it
    asm volatile("barrier.cluster.arrive.aligned;" ::: "memory");
    asm volatile("barrier.cluster.wait.aligned;" ::: "memory");
}

// ---------------- misc small kernels ----------------
__global__ void fill_cls(const float* __restrict__ ct, float* __restrict__ tok)
{
    int i = blockIdx.x * blockDim.x + threadIdx.x;
    if (i >= BB*NCT*HH) return;
    int n = i & (HH-1);
    int c = (i >> 8) % NCT;
    int b = i / (NCT*HH);
    tok[((size_t)(b*LL + c)) * HH + n] = ct[c*HH + n];
}

__global__ void head_kernel(const float* __restrict__ tok, const float* __restrict__ cw,
                            const float* __restrict__ cb, float* __restrict__ out)
{
    int m = blockIdx.x;           // 0..BL-1
    int lane = threadIdx.x;       // 32
    int b = m / LL, l = m % LL;
    __shared__ float tr[HH];
    const float* trow = tok + (size_t)m * HH;
    for (int i = lane; i < HH; i += 32) tr[i] = trow[i];
    __syncwarp();
    if (l < NCT) {
        float sum = 0.f;
        for (int i = lane; i < HH; i += 32) sum += tr[i] * cw[l*HH + i];
#pragma unroll
        for (int o = 16; o; o >>= 1) sum += __shfl_xor_sync(~0u, sum, o);
        if (lane == 0) out[b*NCT + l] = sum + cb[l];
    } else {
        if (lane < NCT) {
            float sum = 0.f;
#pragma unroll 8
            for (int i = 0; i < HH; i++) sum += tr[i] * cw[lane*HH + i];
            out[OUT_FR_OFF + ((size_t)(b*TT + (l - NCT))) * NCT + lane] = sum + cb[lane];
        }
    }
}

__global__ void copy_kernel(const float* __restrict__ src, float* __restrict__ dst, int n)
{
    int i = blockIdx.x * blockDim.x + threadIdx.x;
    if (i < n) dst[i] = src[i];
}

// ---------------- launch ----------------
extern "C" void kernel_launch(void* const* d_in, const int* in_sizes, int n_in,
                              void* d_out, int out_size)
{
    const float* x         = (const float*)d_in[0];
    const float* in_proj_w = (const float*)d_in[2];
    const float* in_proj_b = (const float*)d_in[3];
    const float* pos_emb   = (const float*)d_in[4];
    const float* cls_tok   = (const float*)d_in[5];
    const float* qkv_w     = (const float*)d_in[6];
    const float* qkv_b     = (const float*)d_in[7];
    const float* out_w     = (const float*)d_in[8];
    const float* out_b     = (const float*)d_in[9];
    const float* ln1_g     = (const float*)d_in[10];
    const float* ln1_b     = (const float*)d_in[11];
    const float* ln2_g     = (const float*)d_in[12];
    const float* ln2_b     = (const float*)d_in[13];
    const float* ff1_w     = (const float*)d_in[14];
    const float* ff1_b     = (const float*)d_in[15];
    const float* ff2_w     = (const float*)d_in[16];
    const float* ff2_b     = (const float*)d_in[17];
    const float* lstm_wih  = (const float*)d_in[18];
    const float* lstm_whh  = (const float*)d_in[19];
    const float* lstm_bih  = (const float*)d_in[20];
    const float* lstm_bhh  = (const float*)d_in[21];
    const float* cls_w     = (const float*)d_in[22];
    const float* cls_b     = (const float*)d_in[23];
    float* out = (float*)d_out;

    float *tok, *z, *qkvb, *ob, *ffh, *xg;
    cudaGetSymbolAddress((void**)&tok,  g_tok);
    cudaGetSymbolAddress((void**)&z,    g_z);
    cudaGetSymbolAddress((void**)&qkvb, g_qkv);
    cudaGetSymbolAddress((void**)&ob,   g_o);
    cudaGetSymbolAddress((void**)&ffh,  g_ffh);
    cudaGetSymbolAddress((void**)&xg,   g_xg);

    fill_cls<<<(BB*NCT*HH + 255)/256, 256>>>(cls_tok, tok);
    gemm_tn<3,64><<<dim3(2, 64), 256>>>(x, in_proj_w, in_proj_b, nullptr, pos_emb,
                                        tok, BB*TT, HH, CIN);

    for (int i = 0; i < NLY; i++) {
        if (i == 3) {
            gemm_tn<4,64><<<dim3(8, 65), 256>>>(tok, lstm_wih, lstm_bih, lstm_bhh, nullptr,
                                                xg, BL, 4*HH, HH);
            lstm_rec<<<2*LSTM_CL, 512>>>(xg, lstm_whh, tok);
        }
        ln_kernel<<<BL, HH>>>(tok, ln1_g + i*HH, ln1_b + i*HH, z);
        gemm_tn<0,64><<<dim3(6, 65), 256>>>(z, qkv_w + (size_t)i*3*HH*HH, qkv_b + i*3*HH,
                                            nullptr, nullptr, qkvb, BL, 3*HH, HH);
        int r = 1 << i; if (r > TT-1) r = TT-1;
        attn_kernel2<false><<<BB*NHD*TT, 32>>>(qkvb, ob, r);
        attn_kernel2<true><<<BB*NHD*NCT, 32>>>(qkvb, ob, r);
        gemm_tn<2,64><<<dim3(2, 65), 256>>>(ob, out_w + (size_t)i*HH*HH, out_b + i*HH,
                                            nullptr, nullptr, tok, BL, HH, HH);
        ln_kernel<<<BL, HH>>>(tok, ln2_g + i*HH, ln2_b + i*HH, z);
        gemm_tn<1,64><<<dim3(8, 65), 256>>>(z, ff1_w + (size_t)i*FFD*HH, ff1_b + i*FFD,
                                            nullptr, nullptr, ffh, BL, FFD, HH);
        gemm_tn<2,64><<<dim3(2, 65), 256>>>(ffh, ff2_w + (size_t)i*HH*FFD, ff2_b + i*HH,
                                            nullptr, nullptr, tok, BL, HH, FFD);
    }

    head_kernel<<<BL, 32>>>(tok, cls_w, cls_b, out);
    copy_kernel<<<(BL*HH + 255)/256, 256>>>(tok, out + OUT_TOK_OFF, BL*HH);
}